// round 8
// baseline (speedup 1.0000x reference)
#include <cuda_runtime.h>
#include <cstdint>

#define D_MODEL 1024
#define HIDDEN  64
#define BATCH   8
#define SEQ     4096
#define ROWS    64      // M-tile per block
#define KC      32      // K chunk for 1024-K GEMMs
#define XSTRIDE 36      // 32 + 4 pad words
#define YSTRIDE 68      // 64 + 4 pad words

#define XBUF_W (ROWS * XSTRIDE)     // 2304 words
#define WBUF_W (HIDDEN * XSTRIDE)   // 2304 words
#define STAGE_W (XBUF_W + WBUF_W)   // 4608 words per stage

#define NBLK (BATCH * SEQ / ROWS)   // 512

// Scratch (allocation-free rule: device globals)
__device__ float g_part[NBLK * HIDDEN * 2];   // per-block partials: (se, swv) per col
__device__ float g_w[BATCH * HIDDEN];

__device__ __forceinline__ uint32_t f2tf(float x) {
    uint32_t r;
    asm("cvt.rna.tf32.f32 %0, %1;" : "=r"(r) : "f"(x));
    return r;
}

__device__ __forceinline__ uint32_t smem_u32(const void* p) {
    return (uint32_t)__cvta_generic_to_shared(p);
}

__device__ __forceinline__ void ldsm_x4(uint32_t r[4], uint32_t addr) {
    asm volatile("ldmatrix.sync.aligned.m8n8.x4.shared.b16 {%0,%1,%2,%3}, [%4];"
                 : "=r"(r[0]), "=r"(r[1]), "=r"(r[2]), "=r"(r[3]) : "r"(addr));
}

__device__ __forceinline__ void mma8(float c[4], const uint32_t a[4], const uint32_t b[2]) {
    asm volatile(
        "mma.sync.aligned.m16n8k8.row.col.f32.tf32.tf32.f32 "
        "{%0,%1,%2,%3}, {%4,%5,%6,%7}, {%8,%9}, {%0,%1,%2,%3};\n"
        : "+f"(c[0]), "+f"(c[1]), "+f"(c[2]), "+f"(c[3])
        : "r"(a[0]), "r"(a[1]), "r"(a[2]), "r"(a[3]), "r"(b[0]), "r"(b[1]));
}

// Warp layout: rowg = warp&3 (16 rows at rowg*16), colh = warp>>2 (32 cols at colh*32).
// acc[4][4]: nt = n-tile within the warp's 32-col half.
// A: one LDSM.x4 per k8-step; B: one LDSM.x4 per k8-step per n16-pair (p=0,1).
template<int STRIDE, int KSTEPS>
__device__ __forceinline__ void mma_tile(uint32_t xs, uint32_t ws, float acc[4][4]) {
    const int lane = threadIdx.x & 31;
    const int warp = threadIdx.x >> 5;
    const int rowg = warp & 3;
    const int colh = warp >> 2;
    const uint32_t a_addr = xs +
        ((uint32_t)((rowg * 16 + (lane & 7) + ((lane >> 3) & 1) * 8) * STRIDE
                    + ((lane >> 4) & 1) * 4)) * 4u;
    const uint32_t b_addr = ws +
        ((uint32_t)((colh * 32 + (lane & 7) + ((lane >> 4) & 1) * 8) * STRIDE
                    + ((lane >> 3) & 1) * 4)) * 4u;
#pragma unroll
    for (int ks = 0; ks < KSTEPS; ks++) {
        uint32_t a[4];
        ldsm_x4(a, a_addr + ks * 32);
#pragma unroll
        for (int p = 0; p < 2; p++) {
            uint32_t b[4];
            ldsm_x4(b, b_addr + (uint32_t)(p * 16 * STRIDE * 4) + ks * 32);
            mma8(acc[2 * p],     a, b);
            mma8(acc[2 * p + 1], a, b + 2);
        }
    }
}

// Per-thread register staging fragment: X chunk [64x32] + W chunk [64x32]
struct Frag {
    float4 x[2];
    float4 w[2];
};

__device__ __forceinline__ Frag ldg_chunk(const float* __restrict__ X,
                                          const float* __restrict__ W,
                                          int baseRow, int kc) {
    Frag f;
    const int tid = threadIdx.x;
    const int r  = tid >> 3;         // 0..31
    const int c4 = (tid & 7) * 4;    // 0,4,...,28
#pragma unroll
    for (int rr = 0; rr < 2; rr++)
        f.x[rr] = *(const float4*)(X + (size_t)(baseRow + r + rr * 32) * D_MODEL + kc + c4);
#pragma unroll
    for (int rr = 0; rr < 2; rr++)
        f.w[rr] = *(const float4*)(W + (size_t)(r + rr * 32) * D_MODEL + kc + c4);
    return f;
}

__device__ __forceinline__ void sts_chunk(const Frag& f, uint32_t* Xs, uint32_t* Ws) {
    const int tid = threadIdx.x;
    const int r  = tid >> 3;
    const int c4 = (tid & 7) * 4;
#pragma unroll
    for (int rr = 0; rr < 2; rr++) {
        uint4 o; o.x = f2tf(f.x[rr].x); o.y = f2tf(f.x[rr].y); o.z = f2tf(f.x[rr].z); o.w = f2tf(f.x[rr].w);
        *(uint4*)(Xs + (r + rr * 32) * XSTRIDE + c4) = o;
    }
#pragma unroll
    for (int rr = 0; rr < 2; rr++) {
        uint4 o; o.x = f2tf(f.w[rr].x); o.y = f2tf(f.w[rr].y); o.z = f2tf(f.w[rr].z); o.w = f2tf(f.w[rr].w);
        *(uint4*)(Ws + (r + rr * 32) * XSTRIDE + c4) = o;
    }
}

// ---------------- Kernel 1: fused k&v projections + softmax-pool partials ----------------
// Chunk c: even -> value, odd -> key; kc = (c>>1)*KC. 1 barrier per chunk, distance-2 prefetch.
// No max-subtraction: k = key.Wk + bk has |k| << 80, exp cannot overflow.
__global__ void __launch_bounds__(256, 2) kv_fused_kernel(
    const float* __restrict__ key_in, const float* __restrict__ value_in,
    const float* __restrict__ Wk, const float* __restrict__ bk,
    const float* __restrict__ Wv, const float* __restrict__ bv) {
    extern __shared__ uint32_t smem[];
    uint32_t* buf[2] = { smem, smem + STAGE_W };          // each: [X | W]
    float* pt = (float*)(smem + 2 * STAGE_W);             // [8][32*2] per-warp partials

    const int tid  = threadIdx.x;
    const int lane = tid & 31;
    const int warp = tid >> 5;
    const int gid  = lane >> 2;
    const int ctid = lane & 3;
    const int colh = warp >> 2;
    const int baseRow = blockIdx.x * ROWS;

    const uint32_t xs0 = smem_u32(buf[0]), ws0 = xs0 + XBUF_W * 4;
    const uint32_t xs1 = smem_u32(buf[1]), ws1 = xs1 + XBUF_W * 4;

    float accv[4][4] = {};
    float acck[4][4] = {};

    const int NCH = 2 * (D_MODEL / KC);   // 64

    Frag f = ldg_chunk(value_in, Wv, baseRow, 0);
    sts_chunk(f, buf[0], buf[0] + XBUF_W);
    f = ldg_chunk(key_in, Wk, baseRow, 0);

#pragma unroll 2
    for (int c = 0; c < NCH; c++) {
        __syncthreads();    // chunk c visible; all warps done with mma(c-1)
        if (c + 1 < NCH)
            sts_chunk(f, buf[(c + 1) & 1], buf[(c + 1) & 1] + XBUF_W);
        if (c + 2 < NCH) {
            const int m = (c + 2) & 1;
            f = ldg_chunk(m ? key_in : value_in, m ? Wk : Wv, baseRow, ((c + 2) >> 1) * KC);
        }
        if (c & 1) mma_tile<XSTRIDE, KC / 8>(xs1, ws1, acck);
        else       mma_tile<XSTRIDE, KC / 8>(xs0, ws0, accv);
    }

    // partials over this block's 64 rows: se[col] = sum exp(k), swv[col] = sum exp(k)*v
#pragma unroll
    for (int nt = 0; nt < 4; nt++) {
        const int col = colh * 32 + nt * 8 + 2 * ctid;   // absolute col
        const float bk0 = bk[col], bk1 = bk[col + 1];
        const float bv0 = bv[col], bv1 = bv[col + 1];
        const float e0 = __expf(acck[nt][0] + bk0);
        const float e1 = __expf(acck[nt][1] + bk1);
        const float e2 = __expf(acck[nt][2] + bk0);
        const float e3 = __expf(acck[nt][3] + bk1);
        float se0 = e0 + e2;
        float se1 = e1 + e3;
        float sw0 = e0 * (accv[nt][0] + bv0) + e2 * (accv[nt][2] + bv0);
        float sw1 = e1 * (accv[nt][1] + bv1) + e3 * (accv[nt][3] + bv1);
#pragma unroll
        for (int s = 16; s >= 4; s >>= 1) {
            se0 += __shfl_xor_sync(0xffffffffu, se0, s);
            se1 += __shfl_xor_sync(0xffffffffu, se1, s);
            sw0 += __shfl_xor_sync(0xffffffffu, sw0, s);
            sw1 += __shfl_xor_sync(0xffffffffu, sw1, s);
        }
        if (gid == 0) {
            const int lc = nt * 8 + 2 * ctid;            // local col in half
            pt[warp * 64 + 2 * lc]           = se0;
            pt[warp * 64 + 2 * lc + 1]       = sw0;
            pt[warp * 64 + 2 * (lc + 1)]     = se1;
            pt[warp * 64 + 2 * (lc + 1) + 1] = sw1;
        }
    }
    __syncthreads();
    if (tid < HIDDEN) {
        const int ch = tid >> 5;      // col half
        const int lc = tid & 31;
        float se = 0.f, sw = 0.f;
#pragma unroll
        for (int rg = 0; rg < 4; rg++) {
            const int w = ch * 4 + rg;
            se += pt[w * 64 + 2 * lc];
            sw += pt[w * 64 + 2 * lc + 1];
        }
        g_part[(blockIdx.x * HIDDEN + tid) * 2]     = se;
        g_part[(blockIdx.x * HIDDEN + tid) * 2 + 1] = sw;
    }
}

// ---------------- Kernel 2: combine per-block partials -> g_w ----------------
__global__ void __launch_bounds__(512) reduce2_kernel() {
    const int tid = threadIdx.x;         // 512 = 8 batches x 64 cols
    const int b = tid >> 6, h = tid & 63;
    const int BPB = NBLK / BATCH;        // 64 row-blocks per batch
    float se = 0.f, sw = 0.f;
#pragma unroll 4
    for (int i = 0; i < BPB; i++) {
        const int blk = b * BPB + i;
        se += g_part[(blk * HIDDEN + h) * 2];
        sw += g_part[(blk * HIDDEN + h) * 2 + 1];
    }
    g_w[tid] = sw / se;
}

// ---------------- Kernel 3: fused q-proj -> sigmoid*weights -> Wp proj ----------------
__global__ void __launch_bounds__(256, 2) out_kernel(
    const float* __restrict__ query, const float* __restrict__ Wq,
    const float* __restrict__ bq, const float* __restrict__ Wp,
    const float* __restrict__ bp, float* __restrict__ out) {
    extern __shared__ uint32_t smem[];
    uint32_t* buf[2] = { smem, smem + STAGE_W };           // stage 1
    uint32_t* Ys  = smem;                                  // stage 2, aliases stage-1 bufs
    uint32_t* Ps0 = smem + ROWS * YSTRIDE;                 // [64*68]
    uint32_t* Ps1 = Ps0 + HIDDEN * YSTRIDE;

    const int tid  = threadIdx.x;
    const int warp = tid >> 5;
    const int lane = tid & 31;
    const int gid  = lane >> 2;
    const int ctid = lane & 3;
    const int rowg = warp & 3;
    const int colh = warp >> 2;
    const int baseRow = blockIdx.x * ROWS;
    const int bidx = baseRow >> 12;        // 4096 rows per batch

    const uint32_t xs0 = smem_u32(buf[0]), ws0 = xs0 + XBUF_W * 4;
    const uint32_t xs1 = smem_u32(buf[1]), ws1 = xs1 + XBUF_W * 4;

    // ---- stage 1: q = query @ Wq^T, pipelined ----
    float acc[4][4] = {};
    const int NCH = D_MODEL / KC;   // 32
    Frag f = ldg_chunk(query, Wq, baseRow, 0);
    sts_chunk(f, buf[0], buf[0] + XBUF_W);
    f = ldg_chunk(query, Wq, baseRow, KC);

#pragma unroll 2
    for (int c = 0; c < NCH; c++) {
        __syncthreads();
        if (c + 1 < NCH)
            sts_chunk(f, buf[(c + 1) & 1], buf[(c + 1) & 1] + XBUF_W);
        if (c + 2 < NCH)
            f = ldg_chunk(query, Wq, baseRow, (c + 2) * KC);
        if (c & 1) mma_tile<XSTRIDE, KC / 8>(xs1, ws1, acc);
        else       mma_tile<XSTRIDE, KC / 8>(xs0, ws0, acc);
    }
    __syncthreads();   // all mma done before Ys overwrites buf region

    // epilogue: sigmoid(q + bq) * weights -> Ys (tf32)
#pragma unroll
    for (int nt = 0; nt < 4; nt++) {
        const int col = colh * 32 + nt * 8 + 2 * ctid;
        const float b0 = bq[col], b1 = bq[col + 1];
        const float w0 = g_w[bidx * HIDDEN + col], w1 = g_w[bidx * HIDDEN + col + 1];
        const int r = rowg * 16 + gid;
        const float q0 = acc[nt][0] + b0, q1 = acc[nt][1] + b1;
        const float q2 = acc[nt][2] + b0, q3 = acc[nt][3] + b1;
        Ys[r * YSTRIDE + col]           = f2tf(w0 / (1.f + __expf(-q0)));
        Ys[r * YSTRIDE + col + 1]       = f2tf(w1 / (1.f + __expf(-q1)));
        Ys[(r + 8) * YSTRIDE + col]     = f2tf(w0 / (1.f + __expf(-q2)));
        Ys[(r + 8) * YSTRIDE + col + 1] = f2tf(w1 / (1.f + __expf(-q3)));
    }

    const uint32_t ys_u = smem_u32(Ys);
    const uint32_t ps_u[2] = { smem_u32(Ps0), smem_u32(Ps1) };
    uint32_t* PsPtr[2] = { Ps0, Ps1 };

    // ---- stage 2: out = Ys @ Wp^T + bp, 16 chunks of 64 cols, double-buffered Ps ----
    const int pr  = tid >> 2;            // 0..63
    const int pc4 = (tid & 3) * 4;
    float4 pf[4];
#pragma unroll
    for (int cc = 0; cc < 4; cc++)
        pf[cc] = *(const float4*)(Wp + (size_t)pr * HIDDEN + cc * 16 + pc4);
    {
#pragma unroll
        for (int cc = 0; cc < 4; cc++) {
            uint4 o; o.x = f2tf(pf[cc].x); o.y = f2tf(pf[cc].y); o.z = f2tf(pf[cc].z); o.w = f2tf(pf[cc].w);
            *(uint4*)(Ps0 + pr * YSTRIDE + cc * 16 + pc4) = o;
        }
#pragma unroll
        for (int cc = 0; cc < 4; cc++)
            pf[cc] = *(const float4*)(Wp + (size_t)(64 + pr) * HIDDEN + cc * 16 + pc4);
    }

    for (int ncI = 0; ncI < 16; ncI++) {
        __syncthreads();   // Ps[ncI&1] (and Ys on iter 0) visible; prior mma consumers done
        if (ncI + 1 < 16) {
            uint32_t* Pd = PsPtr[(ncI + 1) & 1];
#pragma unroll
            for (int cc = 0; cc < 4; cc++) {
                uint4 o; o.x = f2tf(pf[cc].x); o.y = f2tf(pf[cc].y); o.z = f2tf(pf[cc].z); o.w = f2tf(pf[cc].w);
                *(uint4*)(Pd + pr * YSTRIDE + cc * 16 + pc4) = o;
            }
        }
        if (ncI + 2 < 16) {
#pragma unroll
            for (int cc = 0; cc < 4; cc++)
                pf[cc] = *(const float4*)(Wp + (size_t)((ncI + 2) * 64 + pr) * HIDDEN + cc * 16 + pc4);
        }

        float oacc[4][4] = {};
        mma_tile<YSTRIDE, HIDDEN / 8>(ys_u, ps_u[ncI & 1], oacc);

        const int nc = ncI * 64;
#pragma unroll
        for (int nt = 0; nt < 4; nt++) {
            const int col = nc + colh * 32 + nt * 8 + 2 * ctid;
            const float b0 = bp[col], b1 = bp[col + 1];
            const size_t r0 = (size_t)(baseRow + rowg * 16 + gid);
            *(float2*)(out + r0 * D_MODEL + col) = make_float2(oacc[nt][0] + b0, oacc[nt][1] + b1);
            *(float2*)(out + (r0 + 8) * D_MODEL + col) = make_float2(oacc[nt][2] + b0, oacc[nt][3] + b1);
        }
    }
}

extern "C" void kernel_launch(void* const* d_in, const int* in_sizes, int n_in,
                              void* d_out, int out_size) {
    const float* query = (const float*)d_in[0];
    const float* key_in = (const float*)d_in[1];
    const float* value_in = (const float*)d_in[2];
    const float* Wq = (const float*)d_in[3];
    const float* bq = (const float*)d_in[4];
    const float* Wk = (const float*)d_in[5];
    const float* bk = (const float*)d_in[6];
    const float* Wv = (const float*)d_in[7];
    const float* bv = (const float*)d_in[8];
    const float* Wp = (const float*)d_in[9];
    const float* bp = (const float*)d_in[10];
    float* out = (float*)d_out;

    const int smem_kv  = 2 * STAGE_W * 4 + 8 * 64 * 4;                        // 38912 B
    const int smem_out = (ROWS * YSTRIDE + 2 * HIDDEN * YSTRIDE) * 4;         // 52224 B
    cudaFuncSetAttribute(kv_fused_kernel, cudaFuncAttributeMaxDynamicSharedMemorySize, smem_kv);
    cudaFuncSetAttribute(out_kernel, cudaFuncAttributeMaxDynamicSharedMemorySize, smem_out);

    kv_fused_kernel<<<NBLK, 256, smem_kv>>>(key_in, value_in, Wk, bk, Wv, bv);
    reduce2_kernel<<<1, 512>>>();
    out_kernel<<<NBLK, 256, smem_out>>>(query, Wq, bq, Wp, bp, out);
}

// round 11
// speedup vs baseline: 1.0660x; 1.0660x over previous
#include <cuda_runtime.h>
#include <cstdint>

#define D_MODEL 1024
#define HIDDEN  64
#define BATCH   8
#define SEQ     4096
#define ROWS    128     // M-tile per block
#define THREADS 512     // 16 warps: 8 row-groups x 2 col-halves
#define KC      32      // K chunk for 1024-K GEMMs
#define XSTRIDE 36      // 32 + 4 pad words
#define YSTRIDE 68      // 64 + 4 pad words

#define XBUF_W (ROWS * XSTRIDE)     // 4608 words
#define WBUF_W (HIDDEN * XSTRIDE)   // 2304 words
#define STAGE_W (XBUF_W + WBUF_W)   // 6912 words per stage

#define NBLK (BATCH * SEQ / ROWS)   // 256

// Scratch (allocation-free rule: device globals)
__device__ float g_part[NBLK * HIDDEN * 2];   // per-block partials: (se, swv) per col
__device__ float g_w[BATCH * HIDDEN];

__device__ __forceinline__ uint32_t f2tf(float x) {
    uint32_t r;
    asm("cvt.rna.tf32.f32 %0, %1;" : "=r"(r) : "f"(x));
    return r;
}

__device__ __forceinline__ uint32_t smem_u32(const void* p) {
    return (uint32_t)__cvta_generic_to_shared(p);
}

__device__ __forceinline__ void ldsm_x4(uint32_t r[4], uint32_t addr) {
    asm volatile("ldmatrix.sync.aligned.m8n8.x4.shared.b16 {%0,%1,%2,%3}, [%4];"
                 : "=r"(r[0]), "=r"(r[1]), "=r"(r[2]), "=r"(r[3]) : "r"(addr));
}

__device__ __forceinline__ void mma8(float c[4], const uint32_t a[4], const uint32_t b[2]) {
    asm volatile(
        "mma.sync.aligned.m16n8k8.row.col.f32.tf32.tf32.f32 "
        "{%0,%1,%2,%3}, {%4,%5,%6,%7}, {%8,%9}, {%0,%1,%2,%3};\n"
        : "+f"(c[0]), "+f"(c[1]), "+f"(c[2]), "+f"(c[3])
        : "r"(a[0]), "r"(a[1]), "r"(a[2]), "r"(a[3]), "r"(b[0]), "r"(b[1]));
}

// Warp layout: rowg = warp&7 (16 rows at rowg*16), colh = warp>>3 (32 cols at colh*32).
// acc[4][4]: nt = n-tile within the warp's 32-col half.
template<int STRIDE, int KSTEPS>
__device__ __forceinline__ void mma_tile(uint32_t xs, uint32_t ws, float acc[4][4]) {
    const int lane = threadIdx.x & 31;
    const int warp = threadIdx.x >> 5;
    const int rowg = warp & 7;
    const int colh = warp >> 3;
    const uint32_t a_addr = xs +
        ((uint32_t)((rowg * 16 + (lane & 7) + ((lane >> 3) & 1) * 8) * STRIDE
                    + ((lane >> 4) & 1) * 4)) * 4u;
    const uint32_t b_addr = ws +
        ((uint32_t)((colh * 32 + (lane & 7) + ((lane >> 4) & 1) * 8) * STRIDE
                    + ((lane >> 3) & 1) * 4)) * 4u;
#pragma unroll
    for (int ks = 0; ks < KSTEPS; ks++) {
        uint32_t a[4];
        ldsm_x4(a, a_addr + ks * 32);
#pragma unroll
        for (int p = 0; p < 2; p++) {
            uint32_t b[4];
            ldsm_x4(b, b_addr + (uint32_t)(p * 16 * STRIDE * 4) + ks * 32);
            mma8(acc[2 * p],     a, b);
            mma8(acc[2 * p + 1], a, b + 2);
        }
    }
}

// Per-thread register staging fragment (512 threads): X chunk [128x32] + W chunk [64x32]
struct Frag {
    float4 x[2];
    float4 w;
};

__device__ __forceinline__ Frag ldg_chunk(const float* __restrict__ X,
                                          const float* __restrict__ W,
                                          int baseRow, int kc) {
    Frag f;
    const int tid = threadIdx.x;
    const int r  = tid >> 3;         // 0..63
    const int c4 = (tid & 7) * 4;    // 0,4,...,28
#pragma unroll
    for (int rr = 0; rr < 2; rr++)
        f.x[rr] = *(const float4*)(X + (size_t)(baseRow + r + rr * 64) * D_MODEL + kc + c4);
    f.w = *(const float4*)(W + (size_t)r * D_MODEL + kc + c4);
    return f;
}

__device__ __forceinline__ void sts_chunk(const Frag& f, uint32_t* Xs, uint32_t* Ws) {
    const int tid = threadIdx.x;
    const int r  = tid >> 3;
    const int c4 = (tid & 7) * 4;
#pragma unroll
    for (int rr = 0; rr < 2; rr++) {
        uint4 o; o.x = f2tf(f.x[rr].x); o.y = f2tf(f.x[rr].y); o.z = f2tf(f.x[rr].z); o.w = f2tf(f.x[rr].w);
        *(uint4*)(Xs + (r + rr * 64) * XSTRIDE + c4) = o;
    }
    {
        uint4 o; o.x = f2tf(f.w.x); o.y = f2tf(f.w.y); o.z = f2tf(f.w.z); o.w = f2tf(f.w.w);
        *(uint4*)(Ws + r * XSTRIDE + c4) = o;
    }
}

// ---------------- Kernel 1: fused k&v projections + softmax-pool partials ----------------
// Chunk c: even -> value, odd -> key; kc = (c>>1)*KC. 1 barrier per chunk, distance-2 prefetch.
// No max-subtraction: k = key.Wk + bk has |k| << 80, exp cannot overflow.
__global__ void __launch_bounds__(THREADS, 1) kv_fused_kernel(
    const float* __restrict__ key_in, const float* __restrict__ value_in,
    const float* __restrict__ Wk, const float* __restrict__ bk,
    const float* __restrict__ Wv, const float* __restrict__ bv) {
    extern __shared__ uint32_t smem[];
    uint32_t* buf[2] = { smem, smem + STAGE_W };          // each: [X | W]
    float* pt = (float*)(smem + 2 * STAGE_W);             // [16][64] per-warp partials

    const int tid  = threadIdx.x;
    const int lane = tid & 31;
    const int warp = tid >> 5;
    const int gid  = lane >> 2;
    const int ctid = lane & 3;
    const int colh = warp >> 3;
    const int baseRow = blockIdx.x * ROWS;

    const uint32_t xs0 = smem_u32(buf[0]), ws0 = xs0 + XBUF_W * 4;
    const uint32_t xs1 = smem_u32(buf[1]), ws1 = xs1 + XBUF_W * 4;

    float accv[4][4] = {};
    float acck[4][4] = {};

    const int NCH = 2 * (D_MODEL / KC);   // 64

    Frag f = ldg_chunk(value_in, Wv, baseRow, 0);
    sts_chunk(f, buf[0], buf[0] + XBUF_W);
    f = ldg_chunk(key_in, Wk, baseRow, 0);

#pragma unroll 2
    for (int c = 0; c < NCH; c++) {
        __syncthreads();    // chunk c visible; all warps done with mma(c-1)
        if (c + 1 < NCH)
            sts_chunk(f, buf[(c + 1) & 1], buf[(c + 1) & 1] + XBUF_W);
        if (c + 2 < NCH) {
            const int m = (c + 2) & 1;
            f = ldg_chunk(m ? key_in : value_in, m ? Wk : Wv, baseRow, ((c + 2) >> 1) * KC);
        }
        if (c & 1) mma_tile<XSTRIDE, KC / 8>(xs1, ws1, acck);
        else       mma_tile<XSTRIDE, KC / 8>(xs0, ws0, accv);
    }

    // partials over this block's 128 rows: se[col] = sum exp(k), swv[col] = sum exp(k)*v
#pragma unroll
    for (int nt = 0; nt < 4; nt++) {
        const int col = colh * 32 + nt * 8 + 2 * ctid;   // absolute col
        const float bk0 = bk[col], bk1 = bk[col + 1];
        const float bv0 = bv[col], bv1 = bv[col + 1];
        const float e0 = __expf(acck[nt][0] + bk0);
        const float e1 = __expf(acck[nt][1] + bk1);
        const float e2 = __expf(acck[nt][2] + bk0);
        const float e3 = __expf(acck[nt][3] + bk1);
        float se0 = e0 + e2;
        float se1 = e1 + e3;
        float sw0 = e0 * (accv[nt][0] + bv0) + e2 * (accv[nt][2] + bv0);
        float sw1 = e1 * (accv[nt][1] + bv1) + e3 * (accv[nt][3] + bv1);
#pragma unroll
        for (int s = 16; s >= 4; s >>= 1) {
            se0 += __shfl_xor_sync(0xffffffffu, se0, s);
            se1 += __shfl_xor_sync(0xffffffffu, se1, s);
            sw0 += __shfl_xor_sync(0xffffffffu, sw0, s);
            sw1 += __shfl_xor_sync(0xffffffffu, sw1, s);
        }
        if (gid == 0) {
            const int lc = nt * 8 + 2 * ctid;            // local col in half
            pt[warp * 64 + 2 * lc]           = se0;
            pt[warp * 64 + 2 * lc + 1]       = sw0;
            pt[warp * 64 + 2 * (lc + 1)]     = se1;
            pt[warp * 64 + 2 * (lc + 1) + 1] = sw1;
        }
    }
    __syncthreads();
    if (tid < HIDDEN) {
        const int ch = tid >> 5;      // col half
        const int lc = tid & 31;
        float se = 0.f, sw = 0.f;
#pragma unroll
        for (int rg = 0; rg < 8; rg++) {
            const int w = ch * 8 + rg;
            se += pt[w * 64 + 2 * lc];
            sw += pt[w * 64 + 2 * lc + 1];
        }
        g_part[(blockIdx.x * HIDDEN + tid) * 2]     = se;
        g_part[(blockIdx.x * HIDDEN + tid) * 2 + 1] = sw;
    }
}

// ---------------- Kernel 2: combine per-block partials -> g_w ----------------
__global__ void __launch_bounds__(512) reduce2_kernel() {
    const int tid = threadIdx.x;         // 512 = 8 batches x 64 cols
    const int b = tid >> 6, h = tid & 63;
    const int BPB = NBLK / BATCH;        // 32 row-blocks per batch
    float se = 0.f, sw = 0.f;
#pragma unroll 4
    for (int i = 0; i < BPB; i++) {
        const int blk = b * BPB + i;
        se += g_part[(blk * HIDDEN + h) * 2];
        sw += g_part[(blk * HIDDEN + h) * 2 + 1];
    }
    g_w[tid] = sw / se;
}

// ---------------- Kernel 3: fused q-proj -> sigmoid*weights -> Wp proj ----------------
__global__ void __launch_bounds__(THREADS, 1) out_kernel(
    const float* __restrict__ query, const float* __restrict__ Wq,
    const float* __restrict__ bq, const float* __restrict__ Wp,
    const float* __restrict__ bp, float* __restrict__ out) {
    extern __shared__ uint32_t smem[];
    uint32_t* buf[2] = { smem, smem + STAGE_W };           // stage 1
    uint32_t* Ys  = smem;                                  // stage 2, aliases stage-1 bufs
    uint32_t* Ps0 = smem + ROWS * YSTRIDE;                 // [64*68]
    uint32_t* Ps1 = Ps0 + HIDDEN * YSTRIDE;

    const int tid  = threadIdx.x;
    const int warp = tid >> 5;
    const int lane = tid & 31;
    const int gid  = lane >> 2;
    const int ctid = lane & 3;
    const int rowg = warp & 7;
    const int colh = warp >> 3;
    const int baseRow = blockIdx.x * ROWS;
    const int bidx = baseRow >> 12;        // 4096 rows per batch

    const uint32_t xs0 = smem_u32(buf[0]), ws0 = xs0 + XBUF_W * 4;
    const uint32_t xs1 = smem_u32(buf[1]), ws1 = xs1 + XBUF_W * 4;

    // ---- stage 1: q = query @ Wq^T, pipelined ----
    float acc[4][4] = {};
    const int NCH = D_MODEL / KC;   // 32
    Frag f = ldg_chunk(query, Wq, baseRow, 0);
    sts_chunk(f, buf[0], buf[0] + XBUF_W);
    f = ldg_chunk(query, Wq, baseRow, KC);

#pragma unroll 2
    for (int c = 0; c < NCH; c++) {
        __syncthreads();
        if (c + 1 < NCH)
            sts_chunk(f, buf[(c + 1) & 1], buf[(c + 1) & 1] + XBUF_W);
        if (c + 2 < NCH)
            f = ldg_chunk(query, Wq, baseRow, (c + 2) * KC);
        if (c & 1) mma_tile<XSTRIDE, KC / 8>(xs1, ws1, acc);
        else       mma_tile<XSTRIDE, KC / 8>(xs0, ws0, acc);
    }
    __syncthreads();   // all mma done before Ys overwrites buf region

    // epilogue: sigmoid(q + bq) * weights -> Ys (tf32)
#pragma unroll
    for (int nt = 0; nt < 4; nt++) {
        const int col = colh * 32 + nt * 8 + 2 * ctid;
        const float b0 = bq[col], b1 = bq[col + 1];
        const float w0 = g_w[bidx * HIDDEN + col], w1 = g_w[bidx * HIDDEN + col + 1];
        const int r = rowg * 16 + gid;
        const float q0 = acc[nt][0] + b0, q1 = acc[nt][1] + b1;
        const float q2 = acc[nt][2] + b0, q3 = acc[nt][3] + b1;
        Ys[r * YSTRIDE + col]           = f2tf(w0 / (1.f + __expf(-q0)));
        Ys[r * YSTRIDE + col + 1]       = f2tf(w1 / (1.f + __expf(-q1)));
        Ys[(r + 8) * YSTRIDE + col]     = f2tf(w0 / (1.f + __expf(-q2)));
        Ys[(r + 8) * YSTRIDE + col + 1] = f2tf(w1 / (1.f + __expf(-q3)));
    }

    const uint32_t ys_u = smem_u32(Ys);
    const uint32_t ps_u[2] = { smem_u32(Ps0), smem_u32(Ps1) };
    uint32_t* PsPtr[2] = { Ps0, Ps1 };

    // ---- stage 2: out = Ys @ Wp^T + bp, 16 chunks of 64 cols, double-buffered Ps ----
    // Ps tile = 64 n-rows x 64 k-words = 1024 float4; 512 threads x 2 float4.
    // fi = tid + e*512: row = fi>>4, word offset = (fi&15)*4.
    float4 pf[2];
#pragma unroll
    for (int e = 0; e < 2; e++) {
        const int fi = tid + e * THREADS;
        pf[e] = *(const float4*)(Wp + (size_t)(fi >> 4) * HIDDEN + (fi & 15) * 4);
    }
    {
#pragma unroll
        for (int e = 0; e < 2; e++) {
            const int fi = tid + e * THREADS;
            uint4 o; o.x = f2tf(pf[e].x); o.y = f2tf(pf[e].y); o.z = f2tf(pf[e].z); o.w = f2tf(pf[e].w);
            *(uint4*)(Ps0 + (fi >> 4) * YSTRIDE + (fi & 15) * 4) = o;
        }
#pragma unroll
        for (int e = 0; e < 2; e++) {
            const int fi = tid + e * THREADS;
            pf[e] = *(const float4*)(Wp + (size_t)(64 + (fi >> 4)) * HIDDEN + (fi & 15) * 4);
        }
    }

    for (int ncI = 0; ncI < 16; ncI++) {
        __syncthreads();   // Ps[ncI&1] (and Ys on iter 0) visible; prior mma consumers done
        if (ncI + 1 < 16) {
            uint32_t* Pd = PsPtr[(ncI + 1) & 1];
#pragma unroll
            for (int e = 0; e < 2; e++) {
                const int fi = tid + e * THREADS;
                uint4 o; o.x = f2tf(pf[e].x); o.y = f2tf(pf[e].y); o.z = f2tf(pf[e].z); o.w = f2tf(pf[e].w);
                *(uint4*)(Pd + (fi >> 4) * YSTRIDE + (fi & 15) * 4) = o;
            }
        }
        if (ncI + 2 < 16) {
#pragma unroll
            for (int e = 0; e < 2; e++) {
                const int fi = tid + e * THREADS;
                pf[e] = *(const float4*)(Wp + (size_t)((ncI + 2) * 64 + (fi >> 4)) * HIDDEN + (fi & 15) * 4);
            }
        }

        float oacc[4][4] = {};
        mma_tile<YSTRIDE, HIDDEN / 8>(ys_u, ps_u[ncI & 1], oacc);

        const int nc = ncI * 64;
#pragma unroll
        for (int nt = 0; nt < 4; nt++) {
            const int col = nc + colh * 32 + nt * 8 + 2 * ctid;
            const float b0 = bp[col], b1 = bp[col + 1];
            const size_t r0 = (size_t)(baseRow + rowg * 16 + gid);
            *(float2*)(out + r0 * D_MODEL + col) = make_float2(oacc[nt][0] + b0, oacc[nt][1] + b1);
            *(float2*)(out + (r0 + 8) * D_MODEL + col) = make_float2(oacc[nt][2] + b0, oacc[nt][3] + b1);
        }
    }
}

extern "C" void kernel_launch(void* const* d_in, const int* in_sizes, int n_in,
                              void* d_out, int out_size) {
    const float* query = (const float*)d_in[0];
    const float* key_in = (const float*)d_in[1];
    const float* value_in = (const float*)d_in[2];
    const float* Wq = (const float*)d_in[3];
    const float* bq = (const float*)d_in[4];
    const float* Wk = (const float*)d_in[5];
    const float* bk = (const float*)d_in[6];
    const float* Wv = (const float*)d_in[7];
    const float* bv = (const float*)d_in[8];
    const float* Wp = (const float*)d_in[9];
    const float* bp = (const float*)d_in[10];
    float* out = (float*)d_out;

    const int smem_kv  = 2 * STAGE_W * 4 + 16 * 64 * 4;                       // 59392 B
    const int smem_out = (ROWS * YSTRIDE + 2 * HIDDEN * YSTRIDE) * 4;         // 69632 B
    cudaFuncSetAttribute(kv_fused_kernel, cudaFuncAttributeMaxDynamicSharedMemorySize, smem_kv);
    cudaFuncSetAttribute(out_kernel, cudaFuncAttributeMaxDynamicSharedMemorySize, smem_out);

    kv_fused_kernel<<<NBLK, THREADS, smem_kv>>>(key_in, value_in, Wk, bk, Wv, bv);
    reduce2_kernel<<<1, 512>>>();
    out_kernel<<<NBLK, THREADS, smem_out>>>(query, Wq, bq, Wp, bp, out);
}

// round 17
// speedup vs baseline: 1.3901x; 1.3041x over previous
#include <cuda_runtime.h>
#include <cstdint>

#define D_MODEL 1024
#define HIDDEN  64
#define BATCH   8
#define SEQ     4096
#define ROWS    128     // M-tile per block
#define THREADS 256     // 8 warps: 4 row-groups (32 rows) x 2 col-halves (32 cols)
#define KC      32
#define XSTRIDE 36      // 32 + 4 pad words
#define YSTRIDE 68      // 64 + 4 pad words

#define XBUF_W (ROWS * XSTRIDE)     // 4608 words
#define WBUF_W (HIDDEN * XSTRIDE)   // 2304 words
#define STAGE_W (XBUF_W + WBUF_W)   // 6912 words per stage

#define NBLK (BATCH * SEQ / ROWS)   // 256

// Scratch (allocation-free rule: device globals)
__device__ float g_part[NBLK * HIDDEN * 2];
__device__ float g_w[BATCH * HIDDEN];

__device__ __forceinline__ uint32_t f2tf(float x) {
    uint32_t r;
    asm("cvt.rna.tf32.f32 %0, %1;" : "=r"(r) : "f"(x));
    return r;
}

__device__ __forceinline__ uint32_t smem_u32(const void* p) {
    return (uint32_t)__cvta_generic_to_shared(p);
}

__device__ __forceinline__ void ldsm_x4(uint32_t r[4], uint32_t addr) {
    asm volatile("ldmatrix.sync.aligned.m8n8.x4.shared.b16 {%0,%1,%2,%3}, [%4];"
                 : "=r"(r[0]), "=r"(r[1]), "=r"(r[2]), "=r"(r[3]) : "r"(addr));
}

__device__ __forceinline__ void mma8(float c[4], const uint32_t a[4], const uint32_t b[2]) {
    asm volatile(
        "mma.sync.aligned.m16n8k8.row.col.f32.tf32.tf32.f32 "
        "{%0,%1,%2,%3}, {%4,%5,%6,%7}, {%8,%9}, {%0,%1,%2,%3};\n"
        : "+f"(c[0]), "+f"(c[1]), "+f"(c[2]), "+f"(c[3])
        : "r"(a[0]), "r"(a[1]), "r"(a[2]), "r"(a[3]), "r"(b[0]), "r"(b[1]));
}

// Warp tile: 32 rows x 32 cols. rowg = warp&3 (rows rowg*32, two m16 tiles),
// colh = warp>>2 (cols colh*32). acc[mt*4 + nt][4], mt=0..1, nt=0..3.
// Per k8-step: 2 A-LDSM + 2 B-LDSM, 8 mma8.
template<int STRIDE, int KSTEPS>
__device__ __forceinline__ void mma_tile(uint32_t xs, uint32_t ws, float acc[8][4]) {
    const int lane = threadIdx.x & 31;
    const int warp = threadIdx.x >> 5;
    const int rowg = warp & 3;
    const int colh = warp >> 2;
    const uint32_t a_addr0 = xs +
        ((uint32_t)((rowg * 32 + (lane & 7) + ((lane >> 3) & 1) * 8) * STRIDE
                    + ((lane >> 4) & 1) * 4)) * 4u;
    const uint32_t a_addr1 = a_addr0 + 16u * STRIDE * 4u;
    const uint32_t b_addr = ws +
        ((uint32_t)((colh * 32 + (lane & 7) + ((lane >> 4) & 1) * 8) * STRIDE
                    + ((lane >> 3) & 1) * 4)) * 4u;
#pragma unroll
    for (int ks = 0; ks < KSTEPS; ks++) {
        uint32_t a0[4], a1[4];
        ldsm_x4(a0, a_addr0 + ks * 32);
        ldsm_x4(a1, a_addr1 + ks * 32);
#pragma unroll
        for (int p = 0; p < 2; p++) {
            uint32_t b[4];
            ldsm_x4(b, b_addr + (uint32_t)(p * 16 * STRIDE * 4) + ks * 32);
            mma8(acc[2 * p],         a0, b);
            mma8(acc[2 * p + 1],     a0, b + 2);
            mma8(acc[4 + 2 * p],     a1, b);
            mma8(acc[4 + 2 * p + 1], a1, b + 2);
        }
    }
}

// Per-thread register staging fragment (256 threads): X chunk [128x32] + W chunk [64x32]
struct Frag {
    float4 x[4];
    float4 w[2];
};

__device__ __forceinline__ Frag ldg_chunk(const float* __restrict__ X,
                                          const float* __restrict__ W,
                                          int baseRow, int kc) {
    Frag f;
    const int tid = threadIdx.x;
    const int r  = tid >> 3;         // 0..31
    const int c4 = (tid & 7) * 4;    // 0,4,...,28
#pragma unroll
    for (int rr = 0; rr < 4; rr++)
        f.x[rr] = *(const float4*)(X + (size_t)(baseRow + r + rr * 32) * D_MODEL + kc + c4);
#pragma unroll
    for (int rr = 0; rr < 2; rr++)
        f.w[rr] = *(const float4*)(W + (size_t)(r + rr * 32) * D_MODEL + kc + c4);
    return f;
}

__device__ __forceinline__ void sts_chunk(const Frag& f, uint32_t* Xs, uint32_t* Ws) {
    const int tid = threadIdx.x;
    const int r  = tid >> 3;
    const int c4 = (tid & 7) * 4;
#pragma unroll
    for (int rr = 0; rr < 4; rr++) {
        uint4 o; o.x = f2tf(f.x[rr].x); o.y = f2tf(f.x[rr].y); o.z = f2tf(f.x[rr].z); o.w = f2tf(f.x[rr].w);
        *(uint4*)(Xs + (r + rr * 32) * XSTRIDE + c4) = o;
    }
#pragma unroll
    for (int rr = 0; rr < 2; rr++) {
        uint4 o; o.x = f2tf(f.w[rr].x); o.y = f2tf(f.w[rr].y); o.z = f2tf(f.w[rr].z); o.w = f2tf(f.w[rr].w);
        *(uint4*)(Ws + (r + rr * 32) * XSTRIDE + c4) = o;
    }
}

// ---------------- Kernel 1: fused k&v projections + softmax-pool partials ----------------
// Chunk c: even -> value, odd -> key; kc = (c>>1)*KC. 1 barrier per chunk, distance-2 prefetch.
// No max-subtraction: k = key.Wk + bk has |k| << 80, exp cannot overflow.
__global__ void __launch_bounds__(THREADS, 2) kv_fused_kernel(
    const float* __restrict__ key_in, const float* __restrict__ value_in,
    const float* __restrict__ Wk, const float* __restrict__ bk,
    const float* __restrict__ Wv, const float* __restrict__ bv) {
    extern __shared__ uint32_t smem[];
    uint32_t* buf[2] = { smem, smem + STAGE_W };          // each: [X | W]
    float* pt = (float*)(smem + 2 * STAGE_W);             // [8][64] per-warp partials

    const int tid  = threadIdx.x;
    const int lane = tid & 31;
    const int warp = tid >> 5;
    const int gid  = lane >> 2;
    const int ctid = lane & 3;
    const int colh = warp >> 2;
    const int baseRow = blockIdx.x * ROWS;

    const uint32_t xs0 = smem_u32(buf[0]), ws0 = xs0 + XBUF_W * 4;
    const uint32_t xs1 = smem_u32(buf[1]), ws1 = xs1 + XBUF_W * 4;

    float accv[8][4] = {};
    float acck[8][4] = {};

    const int NCH = 2 * (D_MODEL / KC);   // 64

    Frag f = ldg_chunk(value_in, Wv, baseRow, 0);
    sts_chunk(f, buf[0], buf[0] + XBUF_W);
    f = ldg_chunk(key_in, Wk, baseRow, 0);

#pragma unroll 2
    for (int c = 0; c < NCH; c++) {
        __syncthreads();    // chunk c visible; all warps done with mma(c-1)
        if (c + 1 < NCH)
            sts_chunk(f, buf[(c + 1) & 1], buf[(c + 1) & 1] + XBUF_W);
        if (c + 2 < NCH) {
            const int m = (c + 2) & 1;
            f = ldg_chunk(m ? key_in : value_in, m ? Wk : Wv, baseRow, ((c + 2) >> 1) * KC);
        }
        if (c & 1) mma_tile<XSTRIDE, KC / 8>(xs1, ws1, acck);
        else       mma_tile<XSTRIDE, KC / 8>(xs0, ws0, accv);
    }

    // partials over this block's 128 rows: se[col] = sum exp(k), swv[col] = sum exp(k)*v
#pragma unroll
    for (int nt = 0; nt < 4; nt++) {
        const int col = colh * 32 + nt * 8 + 2 * ctid;
        const float bk0 = bk[col], bk1 = bk[col + 1];
        const float bv0 = bv[col], bv1 = bv[col + 1];
        float se0 = 0.f, se1 = 0.f, sw0 = 0.f, sw1 = 0.f;
#pragma unroll
        for (int mt = 0; mt < 2; mt++) {
            const int i = mt * 4 + nt;
            const float e0 = __expf(acck[i][0] + bk0);
            const float e1 = __expf(acck[i][1] + bk1);
            const float e2 = __expf(acck[i][2] + bk0);
            const float e3 = __expf(acck[i][3] + bk1);
            se0 += e0 + e2;
            se1 += e1 + e3;
            sw0 += e0 * (accv[i][0] + bv0) + e2 * (accv[i][2] + bv0);
            sw1 += e1 * (accv[i][1] + bv1) + e3 * (accv[i][3] + bv1);
        }
#pragma unroll
        for (int s = 16; s >= 4; s >>= 1) {
            se0 += __shfl_xor_sync(0xffffffffu, se0, s);
            se1 += __shfl_xor_sync(0xffffffffu, se1, s);
            sw0 += __shfl_xor_sync(0xffffffffu, sw0, s);
            sw1 += __shfl_xor_sync(0xffffffffu, sw1, s);
        }
        if (gid == 0) {
            const int lc = nt * 8 + 2 * ctid;            // local col in half
            pt[warp * 64 + 2 * lc]           = se0;
            pt[warp * 64 + 2 * lc + 1]       = sw0;
            pt[warp * 64 + 2 * (lc + 1)]     = se1;
            pt[warp * 64 + 2 * (lc + 1) + 1] = sw1;
        }
    }
    __syncthreads();
    if (tid < HIDDEN) {
        const int ch = tid >> 5;      // col half
        const int lc = tid & 31;
        float se = 0.f, sw = 0.f;
#pragma unroll
        for (int rg = 0; rg < 4; rg++) {
            const int w = ch * 4 + rg;   // warps with colh == ch
            se += pt[w * 64 + 2 * lc];
            sw += pt[w * 64 + 2 * lc + 1];
        }
        g_part[(blockIdx.x * HIDDEN + tid) * 2]     = se;
        g_part[(blockIdx.x * HIDDEN + tid) * 2 + 1] = sw;
    }
}

// ---------------- Kernel 2: combine per-block partials -> g_w ----------------
__global__ void __launch_bounds__(512) reduce2_kernel() {
    const int tid = threadIdx.x;         // 512 = 8 batches x 64 cols
    const int b = tid >> 6, h = tid & 63;
    const int BPB = NBLK / BATCH;        // 32 row-blocks per batch
    float se = 0.f, sw = 0.f;
#pragma unroll 4
    for (int i = 0; i < BPB; i++) {
        const int blk = b * BPB + i;
        se += g_part[(blk * HIDDEN + h) * 2];
        sw += g_part[(blk * HIDDEN + h) * 2 + 1];
    }
    g_w[tid] = sw / se;
}

// ---------------- Kernel 3: fused q-proj -> sigmoid*weights -> Wp proj ----------------
__global__ void __launch_bounds__(THREADS, 2) out_kernel(
    const float* __restrict__ query, const float* __restrict__ Wq,
    const float* __restrict__ bq, const float* __restrict__ Wp,
    const float* __restrict__ bp, float* __restrict__ out) {
    extern __shared__ uint32_t smem[];
    uint32_t* buf[2] = { smem, smem + STAGE_W };           // stage 1
    uint32_t* Ys  = smem;                                  // stage 2, aliases stage-1 bufs
    uint32_t* Ps0 = smem + ROWS * YSTRIDE;                 // [64*68]
    uint32_t* Ps1 = Ps0 + HIDDEN * YSTRIDE;

    const int tid  = threadIdx.x;
    const int warp = tid >> 5;
    const int lane = tid & 31;
    const int gid  = lane >> 2;
    const int ctid = lane & 3;
    const int rowg = warp & 3;
    const int colh = warp >> 2;
    const int baseRow = blockIdx.x * ROWS;
    const int bidx = baseRow >> 12;        // 4096 rows per batch

    const uint32_t xs0 = smem_u32(buf[0]), ws0 = xs0 + XBUF_W * 4;
    const uint32_t xs1 = smem_u32(buf[1]), ws1 = xs1 + XBUF_W * 4;

    // ---- stage 1: q = query @ Wq^T, pipelined ----
    float acc[8][4] = {};
    const int NCH = D_MODEL / KC;   // 32
    Frag f = ldg_chunk(query, Wq, baseRow, 0);
    sts_chunk(f, buf[0], buf[0] + XBUF_W);
    f = ldg_chunk(query, Wq, baseRow, KC);

#pragma unroll 2
    for (int c = 0; c < NCH; c++) {
        __syncthreads();
        if (c + 1 < NCH)
            sts_chunk(f, buf[(c + 1) & 1], buf[(c + 1) & 1] + XBUF_W);
        if (c + 2 < NCH)
            f = ldg_chunk(query, Wq, baseRow, (c + 2) * KC);
        if (c & 1) mma_tile<XSTRIDE, KC / 8>(xs1, ws1, acc);
        else       mma_tile<XSTRIDE, KC / 8>(xs0, ws0, acc);
    }
    __syncthreads();   // all mma done before Ys overwrites buf region

    // epilogue: sigmoid(q + bq) * weights -> Ys (tf32)
#pragma unroll
    for (int nt = 0; nt < 4; nt++) {
        const int col = colh * 32 + nt * 8 + 2 * ctid;
        const float b0 = bq[col], b1 = bq[col + 1];
        const float w0 = g_w[bidx * HIDDEN + col], w1 = g_w[bidx * HIDDEN + col + 1];
#pragma unroll
        for (int mt = 0; mt < 2; mt++) {
            const int i = mt * 4 + nt;
            const int r = rowg * 32 + mt * 16 + gid;
            const float q0 = acc[i][0] + b0, q1 = acc[i][1] + b1;
            const float q2 = acc[i][2] + b0, q3 = acc[i][3] + b1;
            Ys[r * YSTRIDE + col]           = f2tf(w0 / (1.f + __expf(-q0)));
            Ys[r * YSTRIDE + col + 1]       = f2tf(w1 / (1.f + __expf(-q1)));
            Ys[(r + 8) * YSTRIDE + col]     = f2tf(w0 / (1.f + __expf(-q2)));
            Ys[(r + 8) * YSTRIDE + col + 1] = f2tf(w1 / (1.f + __expf(-q3)));
        }
    }

    const uint32_t ys_u = smem_u32(Ys);
    const uint32_t ps_u[2] = { smem_u32(Ps0), smem_u32(Ps1) };
    uint32_t* PsPtr[2] = { Ps0, Ps1 };

    // ---- stage 2: out = Ys @ Wp^T + bp, 16 chunks of 64 cols, double-buffered Ps ----
    // Ps tile = 64 n-rows x 64 k-words; 256 threads x 4 float4.
    const int pr  = tid >> 2;            // 0..63
    const int pc4 = (tid & 3) * 4;
    float4 pf[4];
#pragma unroll
    for (int cc = 0; cc < 4; cc++)
        pf[cc] = *(const float4*)(Wp + (size_t)pr * HIDDEN + cc * 16 + pc4);
    {
#pragma unroll
        for (int cc = 0; cc < 4; cc++) {
            uint4 o; o.x = f2tf(pf[cc].x); o.y = f2tf(pf[cc].y); o.z = f2tf(pf[cc].z); o.w = f2tf(pf[cc].w);
            *(uint4*)(Ps0 + pr * YSTRIDE + cc * 16 + pc4) = o;
        }
#pragma unroll
        for (int cc = 0; cc < 4; cc++)
            pf[cc] = *(const float4*)(Wp + (size_t)(64 + pr) * HIDDEN + cc * 16 + pc4);
    }

    for (int ncI = 0; ncI < 16; ncI++) {
        __syncthreads();   // Ps[ncI&1] (and Ys on iter 0) visible; prior mma consumers done
        if (ncI + 1 < 16) {
            uint32_t* Pd = PsPtr[(ncI + 1) & 1];
#pragma unroll
            for (int cc = 0; cc < 4; cc++) {
                uint4 o; o.x = f2tf(pf[cc].x); o.y = f2tf(pf[cc].y); o.z = f2tf(pf[cc].z); o.w = f2tf(pf[cc].w);
                *(uint4*)(Pd + pr * YSTRIDE + cc * 16 + pc4) = o;
            }
        }
        if (ncI + 2 < 16) {
#pragma unroll
            for (int cc = 0; cc < 4; cc++)
                pf[cc] = *(const float4*)(Wp + (size_t)((ncI + 2) * 64 + pr) * HIDDEN + cc * 16 + pc4);
        }

        float oacc[8][4] = {};
        mma_tile<YSTRIDE, HIDDEN / 8>(ys_u, ps_u[ncI & 1], oacc);

        const int nc = ncI * 64;
#pragma unroll
        for (int nt = 0; nt < 4; nt++) {
            const int col = nc + colh * 32 + nt * 8 + 2 * ctid;
            const float b0 = bp[col], b1 = bp[col + 1];
#pragma unroll
            for (int mt = 0; mt < 2; mt++) {
                const int i = mt * 4 + nt;
                const size_t r0 = (size_t)(baseRow + rowg * 32 + mt * 16 + gid);
                *(float2*)(out + r0 * D_MODEL + col) = make_float2(oacc[i][0] + b0, oacc[i][1] + b1);
                *(float2*)(out + (r0 + 8) * D_MODEL + col) = make_float2(oacc[i][2] + b0, oacc[i][3] + b1);
            }
        }
    }
}

extern "C" void kernel_launch(void* const* d_in, const int* in_sizes, int n_in,
                              void* d_out, int out_size) {
    const float* query = (const float*)d_in[0];
    const float* key_in = (const float*)d_in[1];
    const float* value_in = (const float*)d_in[2];
    const float* Wq = (const float*)d_in[3];
    const float* bq = (const float*)d_in[4];
    const float* Wk = (const float*)d_in[5];
    const float* bk = (const float*)d_in[6];
    const float* Wv = (const float*)d_in[7];
    const float* bv = (const float*)d_in[8];
    const float* Wp = (const float*)d_in[9];
    const float* bp = (const float*)d_in[10];
    float* out = (float*)d_out;

    const int smem_kv  = 2 * STAGE_W * 4 + 8 * 64 * 4;                        // 57344 B
    const int smem_out = (ROWS * YSTRIDE + 2 * HIDDEN * YSTRIDE) * 4;         // 69632 B
    cudaFuncSetAttribute(kv_fused_kernel, cudaFuncAttributeMaxDynamicSharedMemorySize, smem_kv);
    cudaFuncSetAttribute(out_kernel, cudaFuncAttributeMaxDynamicSharedMemorySize, smem_out);

    kv_fused_kernel<<<NBLK, THREADS, smem_kv>>>(key_in, value_in, Wk, bk, Wv, bv);
    reduce2_kernel<<<1, 512>>>();
    out_kernel<<<NBLK, THREADS, smem_out>>>(query, Wq, bq, Wp, bp, out);
}